// round 2
// baseline (speedup 1.0000x reference)
#include <cuda_runtime.h>
#include <cuda_bf16.h>
#include <math.h>

// Problem constants (fixed by the reference setup_inputs)
#define BB 256   // batches
#define AA 64    // atoms
#define EE 128   // edges
#define KK 6     // neighbors
#define HH 256   // hidden

// dynamic smem: weighted rep tile for one batch: 128 * 256 floats = 128 KB
#define SMEM_BYTES (EE * HH * sizeof(float))

__global__ __launch_bounds__(512, 1)
void DirectedEdgeMessage_89885075571226_kernel(
    const float* __restrict__ rep,     // [B, E, H]
    const int*   __restrict__ pairs,   // [B, E, 2]
    const int*   __restrict__ nbrs,    // [B, E, K]
    const float* __restrict__ xyz,     // [B, A, 3]
    float*       __restrict__ out)     // [B, E, H]
{
    extern __shared__ float sm_raw[];          // E*H weighted rep
    __shared__ float s_dist[EE];
    __shared__ int   s_nb[EE * KK];

    const int b   = blockIdx.x;
    const int tid = threadIdx.x;

    // ---- Phase 1: distance weights + stage neighbor indices ----
    if (tid < EE) {
        const int e  = tid;
        const int p0 = pairs[(b * EE + e) * 2 + 0];
        const int p1 = pairs[(b * EE + e) * 2 + 1];
        const float* x0 = xyz + ((size_t)b * AA + p0) * 3;
        const float* x1 = xyz + ((size_t)b * AA + p1) * 3;
        const float dx = x0[0] - x1[0];
        const float dy = x0[1] - x1[1];
        const float dz = x0[2] - x1[2];
        const float d2 = dx * dx + dy * dy + dz * dz;
        const float inv = 1.0f / d2;
        s_dist[e] = isinf(inv) ? 0.0f : inv;
    }
    {
        const int* nb = nbrs + (size_t)b * EE * KK;
        for (int i = tid; i < EE * KK; i += 512)
            s_nb[i] = nb[i];
    }
    __syncthreads();

    // ---- Phase 2: stream rep[b] once, scale by dist, into smem ----
    const float4* __restrict__ repv = (const float4*)(rep + (size_t)b * EE * HH);
    float4* sm = (float4*)sm_raw;
    #pragma unroll
    for (int i = tid; i < EE * HH / 4; i += 512) {   // 8192 float4, 16 iters
        const int e = i >> 6;                        // 64 float4 per row
        const float w = s_dist[e];
        float4 v = repv[i];
        v.x *= w; v.y *= w; v.z *= w; v.w *= w;
        sm[i] = v;
    }
    __syncthreads();

    // ---- Phase 3: K=6 gather-sum out of smem, stream result out ----
    float4* __restrict__ outv = (float4*)(out + (size_t)b * EE * HH);
    #pragma unroll
    for (int i = tid; i < EE * HH / 4; i += 512) {
        const int e  = i >> 6;
        const int h4 = i & 63;
        const int* n = s_nb + e * KK;
        float4 acc = make_float4(0.f, 0.f, 0.f, 0.f);
        #pragma unroll
        for (int k = 0; k < KK; k++) {
            const float4 v = sm[n[k] * (HH / 4) + h4];
            acc.x += v.x; acc.y += v.y; acc.z += v.z; acc.w += v.w;
        }
        outv[i] = acc;
    }
}

extern "C" void kernel_launch(void* const* d_in, const int* in_sizes, int n_in,
                              void* d_out, int out_size)
{
    const float* rep   = (const float*)d_in[0];  // bond_representations [1,B,E,H]
    const int*   pairs = (const int*)  d_in[1];  // bond_pairs [B,E,2]
    const int*   nbrs  = (const int*)  d_in[2];  // bond_neighbors [B,E,K]
    const float* xyz   = (const float*)d_in[3];  // xyz [B,A,3]
    float*       out   = (float*)d_out;          // [1,B,E,H]

    // 128 KB dynamic smem > 48 KB default: opt in (idempotent, not a stream op,
    // safe under graph capture).
    cudaFuncSetAttribute(DirectedEdgeMessage_89885075571226_kernel,
                         cudaFuncAttributeMaxDynamicSharedMemorySize, SMEM_BYTES);

    DirectedEdgeMessage_89885075571226_kernel<<<BB, 512, SMEM_BYTES>>>(
        rep, pairs, nbrs, xyz, out);
}

// round 3
// speedup vs baseline: 1.0017x; 1.0017x over previous
#include <cuda_runtime.h>
#include <cuda_bf16.h>
#include <math.h>

// Problem constants (fixed by the reference setup_inputs)
#define BB 256   // batches
#define AA 64    // atoms
#define EE 128   // edges
#define KK 6     // neighbors
#define HH 256   // hidden

#define HBLK 128                 // H columns per CTA (2 CTAs per batch)
#define NTHREADS 1024
#define SMEM_BYTES (EE * HBLK * sizeof(float))   // 64 KB

__global__ __launch_bounds__(NTHREADS, 2)
void DirectedEdgeMessage_89885075571226_kernel(
    const float* __restrict__ rep,     // [B, E, H]
    const int*   __restrict__ pairs,   // [B, E, 2]
    const int*   __restrict__ nbrs,    // [B, E, K]
    const float* __restrict__ xyz,     // [B, A, 3]
    float*       __restrict__ out)     // [B, E, H]
{
    extern __shared__ float sm_raw[];          // E * HBLK weighted rep slice
    __shared__ float s_dist[EE];
    __shared__ int   s_nb[EE * KK];

    const int hb  = blockIdx.x;                // 0 or 1: which H half
    const int b   = blockIdx.y;                // batch
    const int tid = threadIdx.x;

    // ---- Phase 1: distance weights + stage neighbor indices ----
    if (tid < EE) {
        const int e  = tid;
        const int p0 = pairs[(b * EE + e) * 2 + 0];
        const int p1 = pairs[(b * EE + e) * 2 + 1];
        const float* x0 = xyz + ((size_t)b * AA + p0) * 3;
        const float* x1 = xyz + ((size_t)b * AA + p1) * 3;
        const float dx = x0[0] - x1[0];
        const float dy = x0[1] - x1[1];
        const float dz = x0[2] - x1[2];
        const float d2 = dx * dx + dy * dy + dz * dz;
        const float inv = 1.0f / d2;
        s_dist[e] = isinf(inv) ? 0.0f : inv;
    }
    {
        const int* nb = nbrs + (size_t)b * EE * KK;
        for (int i = tid; i < EE * KK; i += NTHREADS)
            s_nb[i] = nb[i];
    }
    __syncthreads();

    // ---- Phase 2: stream this CTA's H-slice of rep[b], scale by dist ----
    // Row layout in gmem: HH floats; this CTA covers [hb*HBLK, hb*HBLK+HBLK).
    const float4* __restrict__ repv =
        (const float4*)(rep + (size_t)b * EE * HH + (size_t)hb * HBLK);
    float4* sm = (float4*)sm_raw;
    #pragma unroll
    for (int i = tid; i < EE * HBLK / 4; i += NTHREADS) {  // 4096 float4, 4 iters
        const int e  = i >> 5;                             // 32 float4 per slice-row
        const int h4 = i & 31;
        const float w = s_dist[e];
        float4 v = repv[(size_t)e * (HH / 4) + h4];
        v.x *= w; v.y *= w; v.z *= w; v.w *= w;
        sm[i] = v;
    }
    __syncthreads();

    // ---- Phase 3: K=6 gather-sum out of smem, stream result out ----
    float4* __restrict__ outv =
        (float4*)(out + (size_t)b * EE * HH + (size_t)hb * HBLK);
    #pragma unroll
    for (int i = tid; i < EE * HBLK / 4; i += NTHREADS) {
        const int e  = i >> 5;
        const int h4 = i & 31;
        const int* n = s_nb + e * KK;
        float4 acc = make_float4(0.f, 0.f, 0.f, 0.f);
        #pragma unroll
        for (int k = 0; k < KK; k++) {
            const float4 v = sm[n[k] * (HBLK / 4) + h4];
            acc.x += v.x; acc.y += v.y; acc.z += v.z; acc.w += v.w;
        }
        outv[(size_t)e * (HH / 4) + h4] = acc;
    }
}

extern "C" void kernel_launch(void* const* d_in, const int* in_sizes, int n_in,
                              void* d_out, int out_size)
{
    const float* rep   = (const float*)d_in[0];  // bond_representations [1,B,E,H]
    const int*   pairs = (const int*)  d_in[1];  // bond_pairs [B,E,2]
    const int*   nbrs  = (const int*)  d_in[2];  // bond_neighbors [B,E,K]
    const float* xyz   = (const float*)d_in[3];  // xyz [B,A,3]
    float*       out   = (float*)d_out;          // [1,B,E,H]

    cudaFuncSetAttribute(DirectedEdgeMessage_89885075571226_kernel,
                         cudaFuncAttributeMaxDynamicSharedMemorySize, SMEM_BYTES);

    dim3 grid(HH / HBLK, BB);                    // (2, 256) = 512 CTAs
    DirectedEdgeMessage_89885075571226_kernel<<<grid, NTHREADS, SMEM_BYTES>>>(
        rep, pairs, nbrs, xyz, out);
}

// round 5
// speedup vs baseline: 1.1045x; 1.1026x over previous
#include <cuda_runtime.h>
#include <cuda_bf16.h>
#include <cstdint>
#include <math.h>

// Problem constants (fixed by the reference setup_inputs)
#define BB 256   // batches
#define AA 64    // atoms
#define EE 128   // edges
#define KK 6     // neighbors
#define HH 256   // hidden

#define HBLK 64                   // H columns per tile
#define ROW4 (HBLK / 4)           // 16 float4 per tile row
#define TILES_PER_B (HH / HBLK)   // 4
#define NTILES (BB * TILES_PER_B) // 1024
#define NTHREADS 512
#define NCTAS 304                 // 2 per SM on 152-SM GB300
#define TILE_F4 (EE * ROW4)       // 2048 float4 = 32 KB

struct SmemLayout {
    float4 buf[2][TILE_F4];       // raw rep tile, double buffered (64 KB)
    int    nb[2][EE * KK];        // neighbor indices (6 KB)
    float  dist[2][EE];           // per-edge distance weight (1 KB)
};
#define SMEM_BYTES ((int)sizeof(SmemLayout))

__device__ __forceinline__ void cp16(unsigned dst, const void* src) {
    asm volatile("cp.async.cg.shared.global [%0], [%1], 16;" :: "r"(dst), "l"(src));
}

// Stage tile tt into buffer `slot`: rep slice + neighbor indices via cp.async,
// distance weights via regular loads (STS drained by the consumer barrier).
__device__ __forceinline__ void prefetch(
    SmemLayout* sm, int slot, int tt,
    const float* __restrict__ rep, const int* __restrict__ pairs,
    const int* __restrict__ nbrs, const float* __restrict__ xyz, int tid)
{
    const int b  = tt >> 2;       // TILES_PER_B = 4
    const int hb = tt & 3;

    // rep slice: 128 rows x 64 floats = 2048 16B segments
    const char* src_base = (const char*)(rep + (size_t)b * EE * HH + hb * HBLK);
    unsigned dst_base = (unsigned)__cvta_generic_to_shared(&sm->buf[slot][0]);
    #pragma unroll
    for (int p = 0; p < TILE_F4 / NTHREADS; p++) {      // 4 iters
        const int s   = tid + p * NTHREADS;
        const int row = s >> 4;
        const int seg = s & 15;
        cp16(dst_base + s * 16, src_base + (size_t)row * HH * 4 + seg * 16);
    }

    // neighbor indices: 128*6 ints = 3072 B = 192 x 16B
    if (tid < EE * KK / 4) {
        const char* src = (const char*)(nbrs + (size_t)b * EE * KK) + tid * 16;
        unsigned dst = (unsigned)__cvta_generic_to_shared(&sm->nb[slot][0]) + tid * 16;
        cp16(dst, src);
    }

    // distance weights (overlaps with the concurrent gather of the other slot)
    if (tid < EE) {
        const int e  = tid;
        const int p0 = pairs[(b * EE + e) * 2 + 0];
        const int p1 = pairs[(b * EE + e) * 2 + 1];
        const float* x0 = xyz + ((size_t)b * AA + p0) * 3;
        const float* x1 = xyz + ((size_t)b * AA + p1) * 3;
        const float dx = x0[0] - x1[0];
        const float dy = x0[1] - x1[1];
        const float dz = x0[2] - x1[2];
        const float d2 = dx * dx + dy * dy + dz * dz;
        const float inv = 1.0f / d2;
        sm->dist[slot][e] = isinf(inv) ? 0.0f : inv;
    }

    asm volatile("cp.async.commit_group;" ::: "memory");
}

__global__ __launch_bounds__(NTHREADS, 2)
void DirectedEdgeMessage_89885075571226_kernel(
    const float* __restrict__ rep,     // [B, E, H]
    const int*   __restrict__ pairs,   // [B, E, 2]
    const int*   __restrict__ nbrs,    // [B, E, K]
    const float* __restrict__ xyz,     // [B, A, 3]
    float*       __restrict__ out)     // [B, E, H]
{
    extern __shared__ char smraw[];
    SmemLayout* sm = (SmemLayout*)smraw;
    const int tid = threadIdx.x;

    int tt = blockIdx.x;
    if (tt >= NTILES) return;

    prefetch(sm, 0, tt, rep, pairs, nbrs, xyz, tid);
    int slot = 0;

    while (true) {
        const int  ttn  = tt + gridDim.x;
        const bool more = (ttn < NTILES);

        if (more) {
            prefetch(sm, slot ^ 1, ttn, rep, pairs, nbrs, xyz, tid);
            asm volatile("cp.async.wait_group 1;" ::: "memory");
        } else {
            asm volatile("cp.async.wait_group 0;" ::: "memory");
        }
        __syncthreads();

        // ---- gather tile tt from smem slot ----
        const int b  = tt >> 2;
        const int hb = tt & 3;
        float4* __restrict__ outv =
            (float4*)(out + (size_t)b * EE * HH + hb * HBLK);
        const float4* __restrict__ buf = sm->buf[slot];
        const int*    __restrict__ nbp = sm->nb[slot];
        const float*  __restrict__ dsp = sm->dist[slot];

        #pragma unroll
        for (int p = 0; p < TILE_F4 / NTHREADS; p++) {   // 4 iters
            const int i  = tid + p * NTHREADS;
            const int e  = i >> 4;
            const int h4 = i & 15;
            const int* n = nbp + e * KK;
            float4 acc = make_float4(0.f, 0.f, 0.f, 0.f);
            #pragma unroll
            for (int k = 0; k < KK; k++) {
                const int   nk = n[k];
                const float w  = dsp[nk];
                const float4 v = buf[nk * ROW4 + h4];
                acc.x = fmaf(w, v.x, acc.x);
                acc.y = fmaf(w, v.y, acc.y);
                acc.z = fmaf(w, v.z, acc.z);
                acc.w = fmaf(w, v.w, acc.w);
            }
            outv[(size_t)e * (HH / 4) + h4] = acc;
        }

        if (!more) break;
        __syncthreads();          // buffer tt's slot is reused 2 tiles later
        tt = ttn;
        slot ^= 1;
    }
}

extern "C" void kernel_launch(void* const* d_in, const int* in_sizes, int n_in,
                              void* d_out, int out_size)
{
    const float* rep   = (const float*)d_in[0];  // bond_representations [1,B,E,H]
    const int*   pairs = (const int*)  d_in[1];  // bond_pairs [B,E,2]
    const int*   nbrs  = (const int*)  d_in[2];  // bond_neighbors [B,E,K]
    const float* xyz   = (const float*)d_in[3];  // xyz [B,A,3]
    float*       out   = (float*)d_out;          // [1,B,E,H]

    cudaFuncSetAttribute(DirectedEdgeMessage_89885075571226_kernel,
                         cudaFuncAttributeMaxDynamicSharedMemorySize, SMEM_BYTES);

    DirectedEdgeMessage_89885075571226_kernel<<<NCTAS, NTHREADS, SMEM_BYTES>>>(
        rep, pairs, nbrs, xyz, out);
}

// round 7
// speedup vs baseline: 1.1341x; 1.0268x over previous
#include <cuda_runtime.h>
#include <cuda_bf16.h>
#include <cstdint>
#include <math.h>

// Problem constants (fixed by the reference setup_inputs)
#define BB 256   // batches
#define AA 64    // atoms
#define EE 128   // edges
#define KK 6     // neighbors
#define HH 256   // hidden

#define HBLK 64                   // H columns per tile
#define ROW4 (HBLK / 4)           // 16 float4 per tile row
#define TILES_PER_B (HH / HBLK)   // 4
#define NTILES (BB * TILES_PER_B) // 1024 CTAs, one tile each
#define NTHREADS 256
#define TILE_F4 (EE * ROW4)       // 2048 float4 = 32 KB

struct SmemLayout {
    float4 buf[TILE_F4];          // raw rep tile (32 KB)
    int    nb[EE * KK];           // neighbor indices (3 KB)
    float  dist[EE];              // per-edge distance weight (0.5 KB)
};
#define SMEM_BYTES ((int)sizeof(SmemLayout))

__device__ __forceinline__ void cp16(unsigned dst, const void* src) {
    asm volatile("cp.async.cg.shared.global [%0], [%1], 16;" :: "r"(dst), "l"(src));
}

__global__ __launch_bounds__(NTHREADS)
void DirectedEdgeMessage_89885075571226_kernel(
    const float* __restrict__ rep,     // [B, E, H]
    const int*   __restrict__ pairs,   // [B, E, 2]
    const int*   __restrict__ nbrs,    // [B, E, K]
    const float* __restrict__ xyz,     // [B, A, 3]
    float*       __restrict__ out)     // [B, E, H]
{
    extern __shared__ char smraw[];
    SmemLayout* sm = (SmemLayout*)smraw;
    const int tid = threadIdx.x;
    const int b   = blockIdx.x >> 2;           // TILES_PER_B = 4
    const int hb  = blockIdx.x & 3;

    // ---- Issue async tile load first (latency overlapped with dist calc) ----
    // rep slice: 128 rows x 64 floats = 2048 16B segments
    const char* src_base = (const char*)(rep + (size_t)b * EE * HH + hb * HBLK);
    unsigned dst_base = (unsigned)__cvta_generic_to_shared(&sm->buf[0]);
    #pragma unroll
    for (int p = 0; p < TILE_F4 / NTHREADS; p++) {   // 8 iters
        const int s   = tid + p * NTHREADS;
        const int row = s >> 4;
        const int seg = s & 15;
        cp16(dst_base + s * 16, src_base + (size_t)row * HH * 4 + seg * 16);
    }
    // neighbor indices: 128*6 ints = 3072 B = 192 x 16B
    if (tid < EE * KK / 4) {
        const char* src = (const char*)(nbrs + (size_t)b * EE * KK) + tid * 16;
        unsigned dst = (unsigned)__cvta_generic_to_shared(&sm->nb[0]) + tid * 16;
        cp16(dst, src);
    }
    asm volatile("cp.async.commit_group;" ::: "memory");

    // ---- Distance weights (LDG latency hides under the cp.async stream) ----
    if (tid < EE) {
        const int e  = tid;
        const int p0 = pairs[(b * EE + e) * 2 + 0];
        const int p1 = pairs[(b * EE + e) * 2 + 1];
        const float* x0 = xyz + ((size_t)b * AA + p0) * 3;
        const float* x1 = xyz + ((size_t)b * AA + p1) * 3;
        const float dx = x0[0] - x1[0];
        const float dy = x0[1] - x1[1];
        const float dz = x0[2] - x1[2];
        const float d2 = dx * dx + dy * dy + dz * dz;
        const float inv = 1.0f / d2;
        sm->dist[e] = isinf(inv) ? 0.0f : inv;
    }

    asm volatile("cp.async.wait_group 0;" ::: "memory");
    __syncthreads();

    // ---- K=6 gather-sum out of smem, stream result out ----
    float4* __restrict__ outv =
        (float4*)(out + (size_t)b * EE * HH + hb * HBLK);
    const float4* __restrict__ buf = sm->buf;
    const int*    __restrict__ nbp = sm->nb;
    const float*  __restrict__ dsp = sm->dist;

    #pragma unroll
    for (int p = 0; p < TILE_F4 / NTHREADS; p++) {   // 8 iters
        const int i  = tid + p * NTHREADS;
        const int e  = i >> 4;                       // 16 lanes per edge row:
        const int h4 = i & 15;                       // conflict-free 256B spans
        const int* n = nbp + e * KK;
        float4 acc = make_float4(0.f, 0.f, 0.f, 0.f);
        #pragma unroll
        for (int k = 0; k < KK; k++) {
            const int   nk = n[k];                   // broadcast within 16 lanes
            const float w  = dsp[nk];                // broadcast
            const float4 v = buf[nk * ROW4 + h4];
            acc.x = fmaf(w, v.x, acc.x);
            acc.y = fmaf(w, v.y, acc.y);
            acc.z = fmaf(w, v.z, acc.z);
            acc.w = fmaf(w, v.w, acc.w);
        }
        outv[(size_t)e * (HH / 4) + h4] = acc;
    }
}

extern "C" void kernel_launch(void* const* d_in, const int* in_sizes, int n_in,
                              void* d_out, int out_size)
{
    const float* rep   = (const float*)d_in[0];  // bond_representations [1,B,E,H]
    const int*   pairs = (const int*)  d_in[1];  // bond_pairs [B,E,2]
    const int*   nbrs  = (const int*)  d_in[2];  // bond_neighbors [B,E,K]
    const float* xyz   = (const float*)d_in[3];  // xyz [B,A,3]
    float*       out   = (float*)d_out;          // [1,B,E,H]

    cudaFuncSetAttribute(DirectedEdgeMessage_89885075571226_kernel,
                         cudaFuncAttributeMaxDynamicSharedMemorySize, SMEM_BYTES);

    DirectedEdgeMessage_89885075571226_kernel<<<NTILES, NTHREADS, SMEM_BYTES>>>(
        rep, pairs, nbrs, xyz, out);
}